// round 1
// baseline (speedup 1.0000x reference)
#include <cuda_runtime.h>
#include <cuda_bf16.h>

#define N_NODES 100000
#define DIM 64
#define N_EDGES 1200000

// Scratch (allocation-free rule: __device__ globals)
__device__ float g_t[N_NODES * DIM];     // neighbor-transformed features h@Wn
__device__ float g_acc[N_NODES * DIM];   // pre-activation accumulator

// ---------------------------------------------------------------------------
// K1: fused dual GEMM.  acc = relu?(in)@Ws + b ; t = relu?(in)@Wn
// Block = 256 threads: j = tid&63 (output column), grp = tid>>6 handles 8 nodes.
// 32 nodes per block. Weights staged in SMEM; g tile staged in SMEM.
// ---------------------------------------------------------------------------
__global__ void __launch_bounds__(256) sage_gemm(
    const float* __restrict__ in,
    float* __restrict__ acc,
    float* __restrict__ t,
    const float* __restrict__ Wself,
    const float* __restrict__ Wneigh,
    const float* __restrict__ bias,
    int relu_in)
{
    __shared__ float sWs[DIM * DIM];
    __shared__ float sWn[DIM * DIM];
    __shared__ float sg[32][DIM];

    const int tid = threadIdx.x;

    // stage weights (4096 floats each), vectorized
    const float4* Ws4 = (const float4*)Wself;
    const float4* Wn4 = (const float4*)Wneigh;
    #pragma unroll
    for (int i = tid; i < DIM * DIM / 4; i += 256) {
        ((float4*)sWs)[i] = Ws4[i];
        ((float4*)sWn)[i] = Wn4[i];
    }

    // stage 32-node g tile (2048 floats = 512 float4), apply relu on load
    const int node0 = blockIdx.x * 32;
    const float4* in4 = (const float4*)(in + (size_t)node0 * DIM);
    #pragma unroll
    for (int i = tid; i < 32 * (DIM / 4); i += 256) {
        float4 v = in4[i];
        if (relu_in) {
            v.x = fmaxf(v.x, 0.f); v.y = fmaxf(v.y, 0.f);
            v.z = fmaxf(v.z, 0.f); v.w = fmaxf(v.w, 0.f);
        }
        ((float4*)sg)[i] = v;
    }
    __syncthreads();

    const int j   = tid & 63;
    const int grp = tid >> 6;   // 0..3, 8 nodes each

    float accs[8], accn[8];
    #pragma unroll
    for (int m = 0; m < 8; m++) { accs[m] = 0.f; accn[m] = 0.f; }

    #pragma unroll 4
    for (int k = 0; k < DIM; k++) {
        const float ws = sWs[k * DIM + j];
        const float wn = sWn[k * DIM + j];
        #pragma unroll
        for (int m = 0; m < 8; m++) {
            const float gv = sg[grp * 8 + m][k];   // broadcast within warp
            accs[m] = fmaf(gv, ws, accs[m]);
            accn[m] = fmaf(gv, wn, accn[m]);
        }
    }

    const float b = bias[j];
    #pragma unroll
    for (int m = 0; m < 8; m++) {
        const size_t node = (size_t)node0 + grp * 8 + m;
        acc[node * DIM + j] = accs[m] + b;
        t[node * DIM + j]   = accn[m];
    }
}

// ---------------------------------------------------------------------------
// K2: scatter-add.  acc[row_e] += w_e * t[col_e]
// 16 lanes per edge, one float4 (16B) per lane -> 256B coalesced gather,
// vectorized L2 reduction red.global.add.v4.f32 (no return trip).
// ---------------------------------------------------------------------------
__global__ void __launch_bounds__(256) sage_scatter(
    const int* __restrict__ row,
    const int* __restrict__ col,
    const float* __restrict__ ew,
    const float* __restrict__ t,
    float* __restrict__ acc)
{
    const int tid  = blockIdx.x * 256 + threadIdx.x;
    const int e    = tid >> 4;
    const int lane = tid & 15;
    if (e >= N_EDGES) return;

    const int   r = row[e];
    const int   c = col[e];
    const float w = ew[e];

    const float4 v = __ldg((const float4*)t + (size_t)c * 16 + lane);
    float* dst = acc + (size_t)r * DIM + lane * 4;

    asm volatile("red.global.add.v4.f32 [%0], {%1, %2, %3, %4};"
                 :: "l"(dst),
                    "f"(v.x * w), "f"(v.y * w), "f"(v.z * w), "f"(v.w * w)
                 : "memory");
}

// ---------------------------------------------------------------------------
// K3: final in-place relu on d_out
// ---------------------------------------------------------------------------
__global__ void __launch_bounds__(256) relu_inplace(float* __restrict__ p)
{
    const int i = blockIdx.x * 256 + threadIdx.x;   // float4 index
    float4 v = ((float4*)p)[i];
    v.x = fmaxf(v.x, 0.f); v.y = fmaxf(v.y, 0.f);
    v.z = fmaxf(v.z, 0.f); v.w = fmaxf(v.w, 0.f);
    ((float4*)p)[i] = v;
}

// ---------------------------------------------------------------------------
extern "C" void kernel_launch(void* const* d_in, const int* in_sizes, int n_in,
                              void* d_out, int out_size)
{
    const float* x     = (const float*)d_in[0];   // [N, 64]
    const int*   ei    = (const int*)  d_in[1];   // [2, E]
    const float* ew    = (const float*)d_in[2];   // [E]
    const float* Wself = (const float*)d_in[3];   // [3, 64, 64]
    const float* Wngh  = (const float*)d_in[4];   // [3, 64, 64]
    const float* bias  = (const float*)d_in[5];   // [3, 64]
    float* out = (float*)d_out;                   // [N, 64]

    const int* row = ei;            // targets (segment ids)
    const int* col = ei + N_EDGES;  // sources

    float *t_ptr, *acc_ptr;
    cudaGetSymbolAddress((void**)&t_ptr,  g_t);
    cudaGetSymbolAddress((void**)&acc_ptr, g_acc);

    const int GEMM_BLOCKS    = N_NODES / 32;                 // 3125 (exact)
    const int SCATTER_BLOCKS = (N_EDGES * 16 + 255) / 256;   // 75000

    // layer 0 (input = x, no relu on input)
    sage_gemm<<<GEMM_BLOCKS, 256>>>(x, acc_ptr, t_ptr, Wself, Wngh, bias, 0);
    sage_scatter<<<SCATTER_BLOCKS, 256>>>(row, col, ew, t_ptr, acc_ptr);

    // layer 1 (relu fused into GEMM read; in-place acc is safe: per-block RAW via SMEM)
    sage_gemm<<<GEMM_BLOCKS, 256>>>(acc_ptr, acc_ptr, t_ptr,
                                    Wself + DIM * DIM, Wngh + DIM * DIM, bias + DIM, 1);
    sage_scatter<<<SCATTER_BLOCKS, 256>>>(row, col, ew, t_ptr, acc_ptr);

    // layer 2 (accumulate directly into d_out)
    sage_gemm<<<GEMM_BLOCKS, 256>>>(acc_ptr, out, t_ptr,
                                    Wself + 2 * DIM * DIM, Wngh + 2 * DIM * DIM, bias + 2 * DIM, 1);
    sage_scatter<<<SCATTER_BLOCKS, 256>>>(row, col, ew, t_ptr, out);

    // final relu
    relu_inplace<<<(N_NODES * DIM / 4) / 256 + 1, 256>>>(out);
}